// round 1
// baseline (speedup 1.0000x reference)
#include <cuda_runtime.h>

#define N_NODES 50000
#define N_EDGES 800000
#define T_DIM   8
#define NF_IN   32
#define NH1     40
#define NH2     64
#define NF_OUT  64

// Scratch (device globals; allocation-free per harness rules)
__device__ __align__(16) float g_bufA[N_NODES * T_DIM * 64];
__device__ __align__(16) float g_bufB[N_NODES * T_DIM * 64];
__device__ __align__(16) float g_agg [N_NODES * T_DIM * 64];
__device__ float g_onorm[N_NODES];
__device__ float g_inorm[N_NODES];
__device__ __align__(16) float g_WcT[3 * 64 * 64];   // [k][i][o]

static inline int cdiv(int a, int b) { return (a + b - 1) / b; }

// ---------------------------------------------------------------------------
__global__ void k_zero(float* __restrict__ p, int n) {
    int i = blockIdx.x * blockDim.x + threadIdx.x;
    int stride = gridDim.x * blockDim.x;
    for (; i < n; i += stride) p[i] = 0.0f;
}

__global__ void k_deg(const int* __restrict__ src, const int* __restrict__ dst) {
    int i = blockIdx.x * blockDim.x + threadIdx.x;
    if (i < N_EDGES) {
        atomicAdd(&g_onorm[src[i]], 1.0f);
        atomicAdd(&g_inorm[dst[i]], 1.0f);
    }
}

__global__ void k_norm() {
    int i = blockIdx.x * blockDim.x + threadIdx.x;
    if (i < N_NODES) {
        g_onorm[i] = rsqrtf(fmaxf(g_onorm[i], 1.0f));
        g_inorm[i] = rsqrtf(fmaxf(g_inorm[i], 1.0f));
    }
}

// temporal_features [N, 32, 8] -> bufA [N, 8, 32]
__global__ void k_transpose(const float* __restrict__ tf) {
    int i = blockIdx.x * blockDim.x + threadIdx.x;
    if (i < N_NODES * 256) {
        int n = i >> 8, r = i & 255;
        int t = r >> 5, f = r & 31;
        g_bufA[i] = tf[n * 256 + f * 8 + t];   // write index == i (t*32+f == r)
    }
}

// agg[dst] += hin[src] * onorm[src]; LC = (T*F)/4 float4 chunks per edge
template<int LC>
__global__ void k_scatter(const int* __restrict__ src, const int* __restrict__ dst,
                          const float* __restrict__ hin, float* __restrict__ agg) {
    int i = blockIdx.x * blockDim.x + threadIdx.x;
    if (i >= N_EDGES * LC) return;
    int e = i / LC;
    int c = i - e * LC;
    int s = __ldg(&src[e]);
    int d = __ldg(&dst[e]);
    float sc = __ldg(&g_onorm[s]);
    const float4* hp = reinterpret_cast<const float4*>(hin) + (size_t)s * LC + c;
    float4 v = __ldg(hp);
    v.x *= sc; v.y *= sc; v.z *= sc; v.w *= sc;
    float* ap = agg + ((size_t)d * LC + c) * 4;
    asm volatile("red.global.add.v4.f32 [%0], {%1, %2, %3, %4};"
                 :: "l"(ap), "f"(v.x), "f"(v.y), "f"(v.z), "f"(v.w) : "memory");
}

// y[n,t,:] = act((agg[n,t,:] * inorm[n]) @ W + b)
// block handles NPB nodes; per node T_DIM * (FOUT/4) threads, 4 outputs each.
template<int FIN, int FOUT, int NPB, bool RELU>
__global__ void k_matmul(const float* __restrict__ xin, const float* __restrict__ W,
                         const float* __restrict__ b, float* __restrict__ yout) {
    constexpr int OG  = FOUT / 4;
    constexpr int TPN = T_DIM * OG;
    __shared__ float xsh[NPB][T_DIM * FIN];

    int local = threadIdx.x % TPN;
    int which = threadIdx.x / TPN;
    int node  = blockIdx.x * NPB + which;

    if (node < N_NODES) {
        float inrm = g_inorm[node];
        const float* xg = xin + (size_t)node * (T_DIM * FIN);
        for (int j = local; j < T_DIM * FIN; j += TPN)
            xsh[which][j] = xg[j] * inrm;
    }
    __syncthreads();
    if (node >= N_NODES) return;

    int t  = local / OG;
    int og = local % OG;
    const float4* W4 = reinterpret_cast<const float4*>(W);
    float4 acc = reinterpret_cast<const float4*>(b)[og];
    const float* xr = &xsh[which][t * FIN];

    #pragma unroll 8
    for (int i = 0; i < FIN; ++i) {
        float xv = xr[i];
        float4 w = __ldg(&W4[i * OG + og]);
        acc.x = fmaf(xv, w.x, acc.x);
        acc.y = fmaf(xv, w.y, acc.y);
        acc.z = fmaf(xv, w.z, acc.z);
        acc.w = fmaf(xv, w.w, acc.w);
    }
    if (RELU) {
        acc.x = fmaxf(acc.x, 0.0f); acc.y = fmaxf(acc.y, 0.0f);
        acc.z = fmaxf(acc.z, 0.0f); acc.w = fmaxf(acc.w, 0.0f);
    }
    float4* yp = reinterpret_cast<float4*>(yout + (size_t)node * (T_DIM * FOUT) + t * FOUT);
    yp[og] = acc;
}

// Wc [o, i, k] -> WcT [k, i, o]
__global__ void k_wct(const float* __restrict__ Wc) {
    int i = blockIdx.x * blockDim.x + threadIdx.x;
    if (i < 3 * 64 * 64) {
        int k = i / 4096, rem = i % 4096;
        int ii = rem / 64, o = rem % 64;
        g_WcT[i] = Wc[(o * 64 + ii) * 3 + k];
    }
}

// out[n, o, t] = bc[o] + sum_{k,i valid} h3[n, t+k-1, i] * WcT[k, i, o]
__global__ void k_conv(const float* __restrict__ h3, const float* __restrict__ bc,
                       float* __restrict__ out) {
    __shared__ float ysh[T_DIM * NF_OUT];   // 512 floats
    int node = blockIdx.x;
    const float* hg = h3 + (size_t)node * (T_DIM * NF_OUT);
    for (int j = threadIdx.x; j < T_DIM * NF_OUT; j += 128)
        ysh[j] = hg[j];
    __syncthreads();

    int t  = threadIdx.x / 16;
    int og = threadIdx.x % 16;
    const float4* Wt4 = reinterpret_cast<const float4*>(g_WcT);
    float4 acc = reinterpret_cast<const float4*>(bc)[og];

    #pragma unroll
    for (int k = 0; k < 3; ++k) {
        int tr = t + k - 1;
        if (tr < 0 || tr >= T_DIM) continue;
        const float* xr = &ysh[tr * 64];
        #pragma unroll 8
        for (int i = 0; i < 64; ++i) {
            float xv = xr[i];
            float4 w = __ldg(&Wt4[(k * 64 + i) * 16 + og]);
            acc.x = fmaf(xv, w.x, acc.x);
            acc.y = fmaf(xv, w.y, acc.y);
            acc.z = fmaf(xv, w.z, acc.z);
            acc.w = fmaf(xv, w.w, acc.w);
        }
    }
    // out layout [n, o, t]
    float* ob = out + (size_t)node * 512 + t;
    int o0 = og * 4;
    ob[(o0 + 0) * 8] = acc.x;
    ob[(o0 + 1) * 8] = acc.y;
    ob[(o0 + 2) * 8] = acc.z;
    ob[(o0 + 3) * 8] = acc.w;
}

// ---------------------------------------------------------------------------
extern "C" void kernel_launch(void* const* d_in, const int* in_sizes, int n_in,
                              void* d_out, int out_size) {
    const float* tf  = (const float*)d_in[0];
    const int*   src = (const int*)  d_in[1];
    const int*   dst = (const int*)  d_in[2];
    const float* W1  = (const float*)d_in[3];
    const float* b1  = (const float*)d_in[4];
    const float* W2  = (const float*)d_in[5];
    const float* b2  = (const float*)d_in[6];
    const float* W3  = (const float*)d_in[7];
    const float* b3  = (const float*)d_in[8];
    const float* Wc  = (const float*)d_in[9];
    const float* bc  = (const float*)d_in[10];
    float* out = (float*)d_out;

    float *bufA, *bufB, *agg, *onorm, *inorm;
    cudaGetSymbolAddress((void**)&bufA,  g_bufA);
    cudaGetSymbolAddress((void**)&bufB,  g_bufB);
    cudaGetSymbolAddress((void**)&agg,   g_agg);
    cudaGetSymbolAddress((void**)&onorm, g_onorm);
    cudaGetSymbolAddress((void**)&inorm, g_inorm);

    const int TB = 256;

    // degrees + norms
    k_zero<<<cdiv(N_NODES, TB), TB>>>(onorm, N_NODES);
    k_zero<<<cdiv(N_NODES, TB), TB>>>(inorm, N_NODES);
    k_deg <<<cdiv(N_EDGES, TB), TB>>>(src, dst);
    k_norm<<<cdiv(N_NODES, TB), TB>>>();

    // transposed input -> bufA [N, 8, 32]
    k_transpose<<<cdiv(N_NODES * 256, TB), TB>>>(tf);

    // conv weight transpose (independent; ready before conv)
    k_wct<<<cdiv(3 * 64 * 64, TB), TB>>>(Wc);

    // ---- layer 1: 32 -> 40, relu ----
    k_zero<<<cdiv(N_NODES * 256, TB), TB>>>(agg, N_NODES * 256);
    k_scatter<64><<<cdiv(N_EDGES * 64, TB), TB>>>(src, dst, bufA, agg);
    k_matmul<32, 40, 3, true><<<cdiv(N_NODES, 3), 240>>>(agg, W1, b1, bufB);

    // ---- layer 2: 40 -> 64, relu ----
    k_zero<<<cdiv(N_NODES * 320, TB), TB>>>(agg, N_NODES * 320);
    k_scatter<80><<<cdiv(N_EDGES * 80, TB), TB>>>(src, dst, bufB, agg);
    k_matmul<40, 64, 2, true><<<cdiv(N_NODES, 2), 256>>>(agg, W2, b2, bufA);

    // ---- layer 3: 64 -> 64, no act ----
    k_zero<<<cdiv(N_NODES * 512, TB), TB>>>(agg, N_NODES * 512);
    k_scatter<128><<<cdiv(N_EDGES * 128, TB), TB>>>(src, dst, bufA, agg);
    k_matmul<64, 64, 2, false><<<cdiv(N_NODES, 2), 256>>>(agg, W3, b3, bufB);

    // ---- conv1d k=3 pad=1 over T, output [N, 64, 8] ----
    k_conv<<<N_NODES, 128>>>(bufB, bc, out);
}

// round 2
// speedup vs baseline: 1.5433x; 1.5433x over previous
#include <cuda_runtime.h>

#define N_NODES 50000
#define N_EDGES 800000
#define T_DIM   8
#define NF_IN   32
#define NH1     40
#define NH2     64
#define NF_OUT  64

// Scratch (device globals; allocation-free per harness rules)
__device__ __align__(16) float g_bufA[N_NODES * T_DIM * 64];
__device__ __align__(16) float g_bufB[N_NODES * T_DIM * 64];
__device__ __align__(16) float g_agg [N_NODES * T_DIM * 64];
__device__ float g_onorm[N_NODES];
__device__ float g_inorm[N_NODES];
__device__ int   g_odeg [N_NODES];
__device__ int   g_indeg[N_NODES];
__device__ int   g_offsets[N_NODES + 1];
__device__ int   g_cursor [N_NODES];
__device__ int   g_esrc [N_EDGES];
__device__ __align__(16) float g_WcT[3 * 64 * 64];   // [k][i][o]

static inline int cdiv(int a, int b) { return (a + b - 1) / b; }

// ---------------------------------------------------------------------------
// Launch 1: zero degree counters + transpose tf [N,32,8] -> bufA [N,8,32]
__global__ void k_prep(const float* __restrict__ tf) {
    int i = blockIdx.x * blockDim.x + threadIdx.x;
    if (i < N_NODES) { g_odeg[i] = 0; g_indeg[i] = 0; }
    if (i < N_NODES * 256) {
        int n = i >> 8, r = i & 255;
        int f = r & 31;                       // t = r >> 5
        g_bufA[i] = tf[n * 256 + f * 8 + (r >> 5)];
    }
}

// Launch 2: integer degree histogram
__global__ void k_deg(const int* __restrict__ src, const int* __restrict__ dst) {
    int i = blockIdx.x * blockDim.x + threadIdx.x;
    if (i < N_EDGES) {
        atomicAdd(&g_odeg[src[i]], 1);
        atomicAdd(&g_indeg[dst[i]], 1);
    }
}

// Launch 3: norms + conv-weight transpose Wc [o,i,k] -> WcT [k,i,o]
__global__ void k_norm_wct(const float* __restrict__ Wc) {
    int i = blockIdx.x * blockDim.x + threadIdx.x;
    if (i < N_NODES) {
        g_onorm[i] = rsqrtf(fmaxf((float)g_odeg[i], 1.0f));
        g_inorm[i] = rsqrtf(fmaxf((float)g_indeg[i], 1.0f));
    } else {
        int j = i - N_NODES;
        if (j < 3 * 64 * 64) {
            int k = j / 4096, rem = j % 4096;
            int ii = rem / 64, o = rem % 64;
            g_WcT[j] = Wc[(o * 64 + ii) * 3 + k];
        }
    }
}

// Launch 4: single-block exclusive scan of in-degrees -> offsets + cursor
__global__ void k_scan() {
    __shared__ int sh[1024];
    __shared__ int s_carry;
    if (threadIdx.x == 0) s_carry = 0;
    __syncthreads();
    for (int base = 0; base < N_NODES; base += 1024) {
        int idx = base + threadIdx.x;
        int v = (idx < N_NODES) ? g_indeg[idx] : 0;
        sh[threadIdx.x] = v;
        __syncthreads();
        int carry = s_carry;
        for (int off = 1; off < 1024; off <<= 1) {
            int t = (threadIdx.x >= off) ? sh[threadIdx.x - off] : 0;
            __syncthreads();
            sh[threadIdx.x] += t;
            __syncthreads();
        }
        if (idx < N_NODES) {
            int excl = carry + sh[threadIdx.x] - v;
            g_offsets[idx] = excl;
            g_cursor[idx]  = excl;
        }
        __syncthreads();
        if (threadIdx.x == 1023) s_carry = carry + sh[1023];
        __syncthreads();
    }
    if (threadIdx.x == 0) g_offsets[N_NODES] = s_carry;
}

// Launch 5: fill CSR edge-source list (sorted by dst bucket)
__global__ void k_fill(const int* __restrict__ src, const int* __restrict__ dst) {
    int i = blockIdx.x * blockDim.x + threadIdx.x;
    if (i < N_EDGES) {
        int pos = atomicAdd(&g_cursor[dst[i]], 1);
        g_esrc[pos] = src[i];
    }
}

// Pull aggregation: one warp per dst node.
// agg[w,:] = inorm[w] * sum_{e in in(w)} hin[src(e),:] * (SRCSCALE ? onorm[src] : 1)
template<int LC, int NCH, bool SRCSCALE>
__global__ void k_pull(const float* __restrict__ hin, float* __restrict__ agg) {
    int w    = (blockIdx.x * blockDim.x + threadIdx.x) >> 5;
    int lane = threadIdx.x & 31;
    if (w >= N_NODES) return;
    int beg = __ldg(&g_offsets[w]);
    int end = __ldg(&g_offsets[w + 1]);

    float4 acc[NCH];
    #pragma unroll
    for (int j = 0; j < NCH; ++j) acc[j] = make_float4(0.f, 0.f, 0.f, 0.f);

    for (int e = beg; e < end; ++e) {
        int s = __ldg(&g_esrc[e]);
        float sc = 1.0f;
        if (SRCSCALE) sc = __ldg(&g_onorm[s]);
        const float4* hp = reinterpret_cast<const float4*>(hin) + (size_t)s * LC;
        #pragma unroll
        for (int j = 0; j < NCH; ++j) {
            int c = lane + j * 32;
            if (c < LC) {
                float4 v = __ldg(&hp[c]);
                if (SRCSCALE) { v.x *= sc; v.y *= sc; v.z *= sc; v.w *= sc; }
                acc[j].x += v.x; acc[j].y += v.y; acc[j].z += v.z; acc[j].w += v.w;
            }
        }
    }
    float inrm = __ldg(&g_inorm[w]);
    float4* ap = reinterpret_cast<float4*>(agg) + (size_t)w * LC;
    #pragma unroll
    for (int j = 0; j < NCH; ++j) {
        int c = lane + j * 32;
        if (c < LC) {
            float4 v = acc[j];
            v.x *= inrm; v.y *= inrm; v.z *= inrm; v.w *= inrm;
            ap[c] = v;
        }
    }
}

// y[n,t,:] = act(agg[n,t,:] @ W + b) * (OSCALE ? onorm[n] : 1)
template<int FIN, int FOUT, int NPB, bool RELU, bool OSCALE>
__global__ void k_matmul(const float* __restrict__ xin, const float* __restrict__ W,
                         const float* __restrict__ b, float* __restrict__ yout) {
    constexpr int OG  = FOUT / 4;
    constexpr int TPN = T_DIM * OG;
    __shared__ float xsh[NPB][T_DIM * FIN];

    int local = threadIdx.x % TPN;
    int which = threadIdx.x / TPN;
    int node  = blockIdx.x * NPB + which;

    if (node < N_NODES) {
        const float* xg = xin + (size_t)node * (T_DIM * FIN);
        for (int j = local; j < T_DIM * FIN; j += TPN)
            xsh[which][j] = xg[j];
    }
    __syncthreads();
    if (node >= N_NODES) return;

    int t  = local / OG;
    int og = local % OG;
    const float4* W4 = reinterpret_cast<const float4*>(W);
    float4 acc = reinterpret_cast<const float4*>(b)[og];
    const float* xr = &xsh[which][t * FIN];

    #pragma unroll 8
    for (int i = 0; i < FIN; ++i) {
        float xv = xr[i];
        float4 w = __ldg(&W4[i * OG + og]);
        acc.x = fmaf(xv, w.x, acc.x);
        acc.y = fmaf(xv, w.y, acc.y);
        acc.z = fmaf(xv, w.z, acc.z);
        acc.w = fmaf(xv, w.w, acc.w);
    }
    if (RELU) {
        acc.x = fmaxf(acc.x, 0.0f); acc.y = fmaxf(acc.y, 0.0f);
        acc.z = fmaxf(acc.z, 0.0f); acc.w = fmaxf(acc.w, 0.0f);
    }
    if (OSCALE) {
        float on = __ldg(&g_onorm[node]);
        acc.x *= on; acc.y *= on; acc.z *= on; acc.w *= on;
    }
    float4* yp = reinterpret_cast<float4*>(yout + (size_t)node * (T_DIM * FOUT) + t * FOUT);
    yp[og] = acc;
}

// out[n, o, t] = bc[o] + sum_{k, i} h3[n, t+k-1, i] * WcT[k, i, o]
__global__ void k_conv(const float* __restrict__ h3, const float* __restrict__ bc,
                       float* __restrict__ out) {
    __shared__ float ysh[T_DIM * NF_OUT];   // input tile [t][i]
    __shared__ float osh[NF_OUT * 9];       // output tile [o][t], padded
    int node = blockIdx.x;
    const float* hg = h3 + (size_t)node * (T_DIM * NF_OUT);
    for (int j = threadIdx.x; j < T_DIM * NF_OUT; j += 128)
        ysh[j] = hg[j];
    __syncthreads();

    int t  = threadIdx.x / 16;
    int og = threadIdx.x % 16;
    const float4* Wt4 = reinterpret_cast<const float4*>(g_WcT);
    float4 acc = reinterpret_cast<const float4*>(bc)[og];

    #pragma unroll
    for (int k = 0; k < 3; ++k) {
        int tr = t + k - 1;
        if (tr < 0 || tr >= T_DIM) continue;
        const float* xr = &ysh[tr * 64];
        #pragma unroll 8
        for (int i = 0; i < 64; ++i) {
            float xv = xr[i];
            float4 w = __ldg(&Wt4[(k * 64 + i) * 16 + og]);
            acc.x = fmaf(xv, w.x, acc.x);
            acc.y = fmaf(xv, w.y, acc.y);
            acc.z = fmaf(xv, w.z, acc.z);
            acc.w = fmaf(xv, w.w, acc.w);
        }
    }
    int o0 = og * 4;
    osh[(o0 + 0) * 9 + t] = acc.x;
    osh[(o0 + 1) * 9 + t] = acc.y;
    osh[(o0 + 2) * 9 + t] = acc.z;
    osh[(o0 + 3) * 9 + t] = acc.w;
    __syncthreads();

    float* ob = out + (size_t)node * 512;
    for (int j = threadIdx.x; j < 512; j += 128)
        ob[j] = osh[(j >> 3) * 9 + (j & 7)];
}

// ---------------------------------------------------------------------------
extern "C" void kernel_launch(void* const* d_in, const int* in_sizes, int n_in,
                              void* d_out, int out_size) {
    const float* tf  = (const float*)d_in[0];
    const int*   src = (const int*)  d_in[1];
    const int*   dst = (const int*)  d_in[2];
    const float* W1  = (const float*)d_in[3];
    const float* b1  = (const float*)d_in[4];
    const float* W2  = (const float*)d_in[5];
    const float* b2  = (const float*)d_in[6];
    const float* W3  = (const float*)d_in[7];
    const float* b3  = (const float*)d_in[8];
    const float* Wc  = (const float*)d_in[9];
    const float* bc  = (const float*)d_in[10];
    float* out = (float*)d_out;

    float *bufA, *bufB, *agg;
    cudaGetSymbolAddress((void**)&bufA, g_bufA);
    cudaGetSymbolAddress((void**)&bufB, g_bufB);
    cudaGetSymbolAddress((void**)&agg,  g_agg);

    const int TB = 256;

    // CSR build + prologue (5 launches so the 6th = k_pull<64> gets profiled)
    k_prep    <<<cdiv(N_NODES * 256, TB), TB>>>(tf);
    k_deg     <<<cdiv(N_EDGES, TB), TB>>>(src, dst);
    k_norm_wct<<<cdiv(N_NODES + 3 * 64 * 64, TB), TB>>>(Wc);
    k_scan    <<<1, 1024>>>();
    k_fill    <<<cdiv(N_EDGES, TB), TB>>>(src, dst);

    // ---- layer 1: 32 -> 40, relu (onorm of input applied in-pull) ----
    k_pull<64, 2, true><<<cdiv(N_NODES * 32, TB), TB>>>(bufA, agg);
    k_matmul<32, 40, 3, true, true><<<cdiv(N_NODES, 3), 240>>>(agg, W1, b1, bufB);

    // ---- layer 2: 40 -> 64, relu ----
    k_pull<80, 3, false><<<cdiv(N_NODES * 32, TB), TB>>>(bufB, agg);
    k_matmul<40, 64, 2, true, true><<<cdiv(N_NODES, 2), 256>>>(agg, W2, b2, bufA);

    // ---- layer 3: 64 -> 64, no act, no out-scale ----
    k_pull<128, 4, false><<<cdiv(N_NODES * 32, TB), TB>>>(bufA, agg);
    k_matmul<64, 64, 2, false, false><<<cdiv(N_NODES, 2), 256>>>(agg, W3, b3, bufB);

    // ---- conv1d k=3 pad=1 over T, output [N, 64, 8] ----
    k_conv<<<N_NODES, 128>>>(bufB, bc, out);
}

// round 5
// speedup vs baseline: 1.6167x; 1.0476x over previous
#include <cuda_runtime.h>

#define N_NODES 50000
#define N_EDGES 800000
#define T_DIM   8
#define NF_IN   32
#define NH1     40
#define NH2     64
#define NF_OUT  64
#define SCAN_NB ((N_NODES + 1023) / 1024)   // 49

// Scratch (device globals; allocation-free per harness rules)
__device__ __align__(16) float g_bufA[N_NODES * T_DIM * 64];
__device__ __align__(16) float g_bufB[N_NODES * T_DIM * 64];
__device__ __align__(16) float g_agg [N_NODES * T_DIM * 64];
__device__ float g_onorm[N_NODES];
__device__ float g_inorm[N_NODES];
__device__ int   g_odeg [N_NODES];
__device__ int   g_indeg[N_NODES];
__device__ int   g_offsets[N_NODES + 1];
__device__ int   g_cursor [N_NODES];
__device__ int   g_bsum [SCAN_NB];
__device__ int   g_esrc [N_EDGES];
__device__ __align__(16) float g_WcT[3 * 64 * 64];   // [k][i][o]

static inline int cdiv(int a, int b) { return (a + b - 1) / b; }

// ---------------------------------------------------------------------------
// Launch 0: zero degree counters + transpose tf [N,32,8] -> bufA [N,8,32]
__global__ void k_prep(const float* __restrict__ tf) {
    int i = blockIdx.x * blockDim.x + threadIdx.x;
    if (i < N_NODES) { g_odeg[i] = 0; g_indeg[i] = 0; }
    if (i < N_NODES * 256) {
        int n = i >> 8, r = i & 255;
        int f = r & 31;                       // t = r >> 5
        g_bufA[i] = tf[n * 256 + f * 8 + (r >> 5)];
    }
}

// Launch 1: integer degree histogram
__global__ void k_deg(const int* __restrict__ src, const int* __restrict__ dst) {
    int i = blockIdx.x * blockDim.x + threadIdx.x;
    if (i < N_EDGES) {
        atomicAdd(&g_odeg[src[i]], 1);
        atomicAdd(&g_indeg[dst[i]], 1);
    }
}

// Launch 2: per-block exclusive scan (shuffle-based), block totals to g_bsum
__global__ void k_scan1() {
    __shared__ int wsum[32];
    int lane = threadIdx.x & 31, wid = threadIdx.x >> 5;
    int idx = blockIdx.x * 1024 + threadIdx.x;
    int v = (idx < N_NODES) ? g_indeg[idx] : 0;
    int x = v;
    #pragma unroll
    for (int o = 1; o < 32; o <<= 1) {
        int y = __shfl_up_sync(0xffffffffu, x, o);
        if (lane >= o) x += y;
    }
    if (lane == 31) wsum[wid] = x;
    __syncthreads();
    if (wid == 0) {
        int s = wsum[lane];
        #pragma unroll
        for (int o = 1; o < 32; o <<= 1) {
            int y = __shfl_up_sync(0xffffffffu, s, o);
            if (lane >= o) s += y;
        }
        wsum[lane] = s;
    }
    __syncthreads();
    int base = (wid > 0) ? wsum[wid - 1] : 0;
    int incl = base + x;
    if (idx < N_NODES) g_offsets[idx] = incl - v;       // block-local exclusive
    if (threadIdx.x == 1023) g_bsum[blockIdx.x] = incl; // block total
}

// Launch 3: scan the 49 block sums (1 warp), write grand total
// FIX vs rounds 3/4: all shuffles execute convergently; the final
// __shfl_sync is hoisted OUT of the lane==0 branch (previous UB corrupted
// g_offsets[N_NODES] -> node 49999's edge range -> rel_err ~5e-3).
__global__ void k_scan2() {
    int lane = threadIdx.x;
    int v0 = (lane < SCAN_NB) ? g_bsum[lane] : 0;
    int v1 = (lane + 32 < SCAN_NB) ? g_bsum[lane + 32] : 0;
    int x0 = v0, x1 = v1;
    #pragma unroll
    for (int o = 1; o < 32; o <<= 1) {
        int y0 = __shfl_up_sync(0xffffffffu, x0, o);
        int y1 = __shfl_up_sync(0xffffffffu, x1, o);
        if (lane >= o) { x0 += y0; x1 += y1; }
    }
    int tot0 = __shfl_sync(0xffffffffu, x0, 31);   // convergent
    int tot1 = __shfl_sync(0xffffffffu, x1, 31);   // convergent (hoisted)
    if (lane < SCAN_NB) g_bsum[lane] = x0 - v0;
    if (lane + 32 < SCAN_NB) g_bsum[lane + 32] = tot0 + x1 - v1;
    if (lane == 0) g_offsets[N_NODES] = tot0 + tot1;
}

// Launch 4: fixup offsets + cursor + norms + conv-weight transpose
__global__ void k_scan3(const float* __restrict__ Wc) {
    int i = blockIdx.x * blockDim.x + threadIdx.x;
    if (i < N_NODES) {
        int off = g_offsets[i] + g_bsum[i >> 10];
        g_offsets[i] = off;
        g_cursor[i]  = off;
        g_onorm[i] = rsqrtf(fmaxf((float)g_odeg[i], 1.0f));
        g_inorm[i] = rsqrtf(fmaxf((float)g_indeg[i], 1.0f));
    } else {
        int j = i - N_NODES;
        if (j < 3 * 64 * 64) {
            int k = j / 4096, rem = j % 4096;
            int ii = rem / 64, o = rem % 64;
            g_WcT[j] = Wc[(o * 64 + ii) * 3 + k];
        }
    }
}

// Launch 5: fill CSR edge-source list (dst-bucketed)
__global__ void k_fill(const int* __restrict__ src, const int* __restrict__ dst) {
    int i = blockIdx.x * blockDim.x + threadIdx.x;
    if (i < N_EDGES) {
        int pos = atomicAdd(&g_cursor[dst[i]], 1);
        g_esrc[pos] = src[i];
    }
}

// Pull aggregation: one warp per dst node, explicit 2-edge unroll.
// agg[w,:] = inorm[w] * sum_{e in in(w)} hin[src(e),:] * (SRCSCALE ? onorm[src] : 1)
template<int LC, int NCH, bool SRCSCALE>
__global__ void k_pull(const float* __restrict__ hin, float* __restrict__ agg) {
    int w    = (blockIdx.x * blockDim.x + threadIdx.x) >> 5;
    int lane = threadIdx.x & 31;
    if (w >= N_NODES) return;
    int beg = __ldg(&g_offsets[w]);
    int end = __ldg(&g_offsets[w + 1]);

    float4 acc[NCH];
    #pragma unroll
    for (int j = 0; j < NCH; ++j) acc[j] = make_float4(0.f, 0.f, 0.f, 0.f);

    int e = beg;
    for (; e + 2 <= end; e += 2) {
        int s0 = __ldg(&g_esrc[e]);
        int s1 = __ldg(&g_esrc[e + 1]);
        float c0 = SRCSCALE ? __ldg(&g_onorm[s0]) : 1.0f;
        float c1 = SRCSCALE ? __ldg(&g_onorm[s1]) : 1.0f;
        const float4* h0 = reinterpret_cast<const float4*>(hin) + (size_t)s0 * LC;
        const float4* h1 = reinterpret_cast<const float4*>(hin) + (size_t)s1 * LC;
        #pragma unroll
        for (int j = 0; j < NCH; ++j) {
            int c = lane + j * 32;
            if (c < LC) {
                float4 a = __ldg(&h0[c]);
                float4 b = __ldg(&h1[c]);
                if (SRCSCALE) {
                    acc[j].x += a.x * c0 + b.x * c1;
                    acc[j].y += a.y * c0 + b.y * c1;
                    acc[j].z += a.z * c0 + b.z * c1;
                    acc[j].w += a.w * c0 + b.w * c1;
                } else {
                    acc[j].x += a.x + b.x;
                    acc[j].y += a.y + b.y;
                    acc[j].z += a.z + b.z;
                    acc[j].w += a.w + b.w;
                }
            }
        }
    }
    if (e < end) {   // remainder (at most one edge)
        int s0 = __ldg(&g_esrc[e]);
        float c0 = SRCSCALE ? __ldg(&g_onorm[s0]) : 1.0f;
        const float4* h0 = reinterpret_cast<const float4*>(hin) + (size_t)s0 * LC;
        #pragma unroll
        for (int j = 0; j < NCH; ++j) {
            int c = lane + j * 32;
            if (c < LC) {
                float4 a = __ldg(&h0[c]);
                if (SRCSCALE) {
                    acc[j].x += a.x * c0; acc[j].y += a.y * c0;
                    acc[j].z += a.z * c0; acc[j].w += a.w * c0;
                } else {
                    acc[j].x += a.x; acc[j].y += a.y;
                    acc[j].z += a.z; acc[j].w += a.w;
                }
            }
        }
    }
    float inrm = __ldg(&g_inorm[w]);
    float4* ap = reinterpret_cast<float4*>(agg) + (size_t)w * LC;
    #pragma unroll
    for (int j = 0; j < NCH; ++j) {
        int c = lane + j * 32;
        if (c < LC) {
            float4 vv = acc[j];
            vv.x *= inrm; vv.y *= inrm; vv.z *= inrm; vv.w *= inrm;
            ap[c] = vv;
        }
    }
}

// y[n,t,:] = act(agg[n,t,:] @ W + b) * (OSCALE ? onorm[n] : 1)
template<int FIN, int FOUT, int NPB, bool RELU, bool OSCALE>
__global__ void k_matmul(const float* __restrict__ xin, const float* __restrict__ W,
                         const float* __restrict__ b, float* __restrict__ yout) {
    constexpr int OG  = FOUT / 4;
    constexpr int TPN = T_DIM * OG;
    __shared__ float xsh[NPB][T_DIM * FIN];

    int local = threadIdx.x % TPN;
    int which = threadIdx.x / TPN;
    int node  = blockIdx.x * NPB + which;

    if (node < N_NODES) {
        const float* xg = xin + (size_t)node * (T_DIM * FIN);
        for (int j = local; j < T_DIM * FIN; j += TPN)
            xsh[which][j] = xg[j];
    }
    __syncthreads();
    if (node >= N_NODES) return;

    int t  = local / OG;
    int og = local % OG;
    const float4* W4 = reinterpret_cast<const float4*>(W);
    float4 acc = reinterpret_cast<const float4*>(b)[og];
    const float* xr = &xsh[which][t * FIN];

    #pragma unroll 8
    for (int i = 0; i < FIN; ++i) {
        float xv = xr[i];
        float4 w = __ldg(&W4[i * OG + og]);
        acc.x = fmaf(xv, w.x, acc.x);
        acc.y = fmaf(xv, w.y, acc.y);
        acc.z = fmaf(xv, w.z, acc.z);
        acc.w = fmaf(xv, w.w, acc.w);
    }
    if (RELU) {
        acc.x = fmaxf(acc.x, 0.0f); acc.y = fmaxf(acc.y, 0.0f);
        acc.z = fmaxf(acc.z, 0.0f); acc.w = fmaxf(acc.w, 0.0f);
    }
    if (OSCALE) {
        float on = __ldg(&g_onorm[node]);
        acc.x *= on; acc.y *= on; acc.z *= on; acc.w *= on;
    }
    float4* yp = reinterpret_cast<float4*>(yout + (size_t)node * (T_DIM * FOUT) + t * FOUT);
    yp[og] = acc;
}

// Fused layer-3 matmul (64->64, no act) + conv1d(k=3, pad=1) -> out [N, 64, 8]
__global__ void k_mm3_conv(const float* __restrict__ xin, const float* __restrict__ W,
                           const float* __restrict__ b, const float* __restrict__ bc,
                           float* __restrict__ out) {
    __shared__ float xsh[2][512];
    __shared__ float ysh[2][512];
    __shared__ float osh[2][576];          // [o][t] padded to 9
    int local = threadIdx.x & 127;
    int which = threadIdx.x >> 7;
    int node  = blockIdx.x * 2 + which;    // 50000 = 25000*2 exact

    // load agg row (coalesced float4)
    {
        const float4* xg = reinterpret_cast<const float4*>(xin + (size_t)node * 512);
        reinterpret_cast<float4*>(xsh[which])[local] = __ldg(&xg[local]);
    }
    __syncthreads();

    int t  = local >> 4;                   // 0..7
    int og = local & 15;                   // 0..15 (float4 output groups)
    const float4* W4 = reinterpret_cast<const float4*>(W);

    // matmul: y[t, og*4..] = x[t,:] @ W + b
    {
        float4 acc = reinterpret_cast<const float4*>(b)[og];
        const float* xr = &xsh[which][t * 64];
        #pragma unroll 8
        for (int i = 0; i < 64; ++i) {
            float xv = xr[i];
            float4 w = __ldg(&W4[i * 16 + og]);
            acc.x = fmaf(xv, w.x, acc.x);
            acc.y = fmaf(xv, w.y, acc.y);
            acc.z = fmaf(xv, w.z, acc.z);
            acc.w = fmaf(xv, w.w, acc.w);
        }
        reinterpret_cast<float4*>(ysh[which])[t * 16 + og] = acc;
    }
    __syncthreads();

    // conv over t with k=3, pad=1
    {
        const float4* Wt4 = reinterpret_cast<const float4*>(g_WcT);
        float4 acc = reinterpret_cast<const float4*>(bc)[og];
        #pragma unroll
        for (int k = 0; k < 3; ++k) {
            int tr = t + k - 1;
            if (tr < 0 || tr >= T_DIM) continue;
            const float* xr = &ysh[which][tr * 64];
            #pragma unroll 8
            for (int i = 0; i < 64; ++i) {
                float xv = xr[i];
                float4 w = __ldg(&Wt4[(k * 64 + i) * 16 + og]);
                acc.x = fmaf(xv, w.x, acc.x);
                acc.y = fmaf(xv, w.y, acc.y);
                acc.z = fmaf(xv, w.z, acc.z);
                acc.w = fmaf(xv, w.w, acc.w);
            }
        }
        int o0 = og * 4;
        osh[which][(o0 + 0) * 9 + t] = acc.x;
        osh[which][(o0 + 1) * 9 + t] = acc.y;
        osh[which][(o0 + 2) * 9 + t] = acc.z;
        osh[which][(o0 + 3) * 9 + t] = acc.w;
    }
    __syncthreads();

    float* ob = out + (size_t)node * 512;
    #pragma unroll
    for (int k = 0; k < 4; ++k) {
        int j = local + k * 128;
        ob[j] = osh[which][(j >> 3) * 9 + (j & 7)];
    }
}

// ---------------------------------------------------------------------------
extern "C" void kernel_launch(void* const* d_in, const int* in_sizes, int n_in,
                              void* d_out, int out_size) {
    const float* tf  = (const float*)d_in[0];
    const int*   src = (const int*)  d_in[1];
    const int*   dst = (const int*)  d_in[2];
    const float* W1  = (const float*)d_in[3];
    const float* b1  = (const float*)d_in[4];
    const float* W2  = (const float*)d_in[5];
    const float* b2  = (const float*)d_in[6];
    const float* W3  = (const float*)d_in[7];
    const float* b3  = (const float*)d_in[8];
    const float* Wc  = (const float*)d_in[9];
    const float* bc  = (const float*)d_in[10];
    float* out = (float*)d_out;

    float *bufA, *bufB, *agg;
    cudaGetSymbolAddress((void**)&bufA, g_bufA);
    cudaGetSymbolAddress((void**)&bufB, g_bufB);
    cudaGetSymbolAddress((void**)&agg,  g_agg);

    const int TB = 256;

    // CSR build + prologue
    k_prep <<<cdiv(N_NODES * 256, TB), TB>>>(tf);
    k_deg  <<<cdiv(N_EDGES, TB), TB>>>(src, dst);
    k_scan1<<<SCAN_NB, 1024>>>();
    k_scan2<<<1, 32>>>();
    k_scan3<<<cdiv(N_NODES + 3 * 64 * 64, TB), TB>>>(Wc);
    k_fill <<<cdiv(N_EDGES, TB), TB>>>(src, dst);

    // ---- layer 1: 32 -> 40, relu (onorm of raw input applied in-pull) ----
    k_pull<64, 2, true><<<cdiv(N_NODES * 32, TB), TB>>>(bufA, agg);
    k_matmul<32, 40, 3, true, true><<<cdiv(N_NODES, 3), 240>>>(agg, W1, b1, bufB);

    // ---- layer 2: 40 -> 64, relu ----
    k_pull<80, 3, false><<<cdiv(N_NODES * 32, TB), TB>>>(bufB, agg);
    k_matmul<40, 64, 2, true, true><<<cdiv(N_NODES, 2), 256>>>(agg, W2, b2, bufA);

    // ---- layer 3: 64 -> 64 + conv1d fused ----
    k_pull<128, 4, false><<<cdiv(N_NODES * 32, TB), TB>>>(bufA, agg);
    k_mm3_conv<<<N_NODES / 2, 256>>>(agg, W3, b3, bc, out);
}

// round 6
// speedup vs baseline: 1.7104x; 1.0579x over previous
#include <cuda_runtime.h>

#define N_NODES 50000
#define N_EDGES 800000
#define T_DIM   8
#define NF_IN   32
#define NH1     40
#define NH2     64
#define NF_OUT  64
#define SCAN_NB ((N_NODES + 1023) / 1024)   // 49

// Scratch (device globals; allocation-free per harness rules)
__device__ __align__(16) float g_bufA[N_NODES * T_DIM * 64];
__device__ __align__(16) float g_bufB[N_NODES * T_DIM * 64];
__device__ float g_onorm[N_NODES];
__device__ float g_inorm[N_NODES];
__device__ int   g_odeg [N_NODES];
__device__ int   g_indeg[N_NODES];
__device__ int   g_offsets[N_NODES + 1];
__device__ int   g_cursor [N_NODES];
__device__ int   g_bsum [SCAN_NB];
__device__ int   g_esrc [N_EDGES];
__device__ __align__(16) float g_WcT[3 * 64 * 64];   // [k][i][o]

static inline int cdiv(int a, int b) { return (a + b - 1) / b; }

// ---------------------------------------------------------------------------
// Launch 0: zero degree counters + transpose tf [N,32,8] -> bufA [N,8,32]
__global__ void k_prep(const float* __restrict__ tf) {
    int i = blockIdx.x * blockDim.x + threadIdx.x;
    if (i < N_NODES) { g_odeg[i] = 0; g_indeg[i] = 0; }
    if (i < N_NODES * 256) {
        int n = i >> 8, r = i & 255;
        int f = r & 31;                       // t = r >> 5
        g_bufA[i] = tf[n * 256 + f * 8 + (r >> 5)];
    }
}

// Launch 1: integer degree histogram
__global__ void k_deg(const int* __restrict__ src, const int* __restrict__ dst) {
    int i = blockIdx.x * blockDim.x + threadIdx.x;
    if (i < N_EDGES) {
        atomicAdd(&g_odeg[src[i]], 1);
        atomicAdd(&g_indeg[dst[i]], 1);
    }
}

// Launch 2: per-block exclusive scan (shuffle-based), block totals to g_bsum
__global__ void k_scan1() {
    __shared__ int wsum[32];
    int lane = threadIdx.x & 31, wid = threadIdx.x >> 5;
    int idx = blockIdx.x * 1024 + threadIdx.x;
    int v = (idx < N_NODES) ? g_indeg[idx] : 0;
    int x = v;
    #pragma unroll
    for (int o = 1; o < 32; o <<= 1) {
        int y = __shfl_up_sync(0xffffffffu, x, o);
        if (lane >= o) x += y;
    }
    if (lane == 31) wsum[wid] = x;
    __syncthreads();
    if (wid == 0) {
        int s = wsum[lane];
        #pragma unroll
        for (int o = 1; o < 32; o <<= 1) {
            int y = __shfl_up_sync(0xffffffffu, s, o);
            if (lane >= o) s += y;
        }
        wsum[lane] = s;
    }
    __syncthreads();
    int base = (wid > 0) ? wsum[wid - 1] : 0;
    int incl = base + x;
    if (idx < N_NODES) g_offsets[idx] = incl - v;       // block-local exclusive
    if (threadIdx.x == 1023) g_bsum[blockIdx.x] = incl; // block total
}

// Launch 3: scan the 49 block sums (1 warp). All shuffles convergent.
__global__ void k_scan2() {
    int lane = threadIdx.x;
    int v0 = (lane < SCAN_NB) ? g_bsum[lane] : 0;
    int v1 = (lane + 32 < SCAN_NB) ? g_bsum[lane + 32] : 0;
    int x0 = v0, x1 = v1;
    #pragma unroll
    for (int o = 1; o < 32; o <<= 1) {
        int y0 = __shfl_up_sync(0xffffffffu, x0, o);
        int y1 = __shfl_up_sync(0xffffffffu, x1, o);
        if (lane >= o) { x0 += y0; x1 += y1; }
    }
    int tot0 = __shfl_sync(0xffffffffu, x0, 31);   // convergent
    int tot1 = __shfl_sync(0xffffffffu, x1, 31);   // convergent
    if (lane < SCAN_NB) g_bsum[lane] = x0 - v0;
    if (lane + 32 < SCAN_NB) g_bsum[lane + 32] = tot0 + x1 - v1;
    if (lane == 0) g_offsets[N_NODES] = tot0 + tot1;
}

// Launch 4: fixup offsets + cursor + norms + conv-weight transpose
__global__ void k_scan3(const float* __restrict__ Wc) {
    int i = blockIdx.x * blockDim.x + threadIdx.x;
    if (i < N_NODES) {
        int off = g_offsets[i] + g_bsum[i >> 10];
        g_offsets[i] = off;
        g_cursor[i]  = off;
        g_onorm[i] = rsqrtf(fmaxf((float)g_odeg[i], 1.0f));
        g_inorm[i] = rsqrtf(fmaxf((float)g_indeg[i], 1.0f));
    } else {
        int j = i - N_NODES;
        if (j < 3 * 64 * 64) {
            int k = j / 4096, rem = j % 4096;
            int ii = rem / 64, o = rem % 64;
            g_WcT[j] = Wc[(o * 64 + ii) * 3 + k];
        }
    }
}

// Launch 5: fill CSR edge-source list (dst-bucketed)
__global__ void k_fill(const int* __restrict__ src, const int* __restrict__ dst) {
    int i = blockIdx.x * blockDim.x + threadIdx.x;
    if (i < N_EDGES) {
        int pos = atomicAdd(&g_cursor[dst[i]], 1);
        g_esrc[pos] = src[i];
    }
}

// ---------------------------------------------------------------------------
// Pull body (round-5 proven code): warp accumulates the node's [T, FIN] tile.
template<int LC, int NCH, bool SRCSCALE>
__device__ __forceinline__ void pull_node(const float* __restrict__ hin,
                                          int w, int lane, float4* acc) {
    int beg = __ldg(&g_offsets[w]);
    int end = __ldg(&g_offsets[w + 1]);
    #pragma unroll
    for (int j = 0; j < NCH; ++j) acc[j] = make_float4(0.f, 0.f, 0.f, 0.f);

    int e = beg;
    for (; e + 2 <= end; e += 2) {
        int s0 = __ldg(&g_esrc[e]);
        int s1 = __ldg(&g_esrc[e + 1]);
        float c0 = SRCSCALE ? __ldg(&g_onorm[s0]) : 1.0f;
        float c1 = SRCSCALE ? __ldg(&g_onorm[s1]) : 1.0f;
        const float4* h0 = reinterpret_cast<const float4*>(hin) + (size_t)s0 * LC;
        const float4* h1 = reinterpret_cast<const float4*>(hin) + (size_t)s1 * LC;
        #pragma unroll
        for (int j = 0; j < NCH; ++j) {
            int c = lane + j * 32;
            if (c < LC) {
                float4 a = __ldg(&h0[c]);
                float4 b = __ldg(&h1[c]);
                if (SRCSCALE) {
                    acc[j].x += a.x * c0 + b.x * c1;
                    acc[j].y += a.y * c0 + b.y * c1;
                    acc[j].z += a.z * c0 + b.z * c1;
                    acc[j].w += a.w * c0 + b.w * c1;
                } else {
                    acc[j].x += a.x + b.x;
                    acc[j].y += a.y + b.y;
                    acc[j].z += a.z + b.z;
                    acc[j].w += a.w + b.w;
                }
            }
        }
    }
    if (e < end) {
        int s0 = __ldg(&g_esrc[e]);
        float c0 = SRCSCALE ? __ldg(&g_onorm[s0]) : 1.0f;
        const float4* h0 = reinterpret_cast<const float4*>(hin) + (size_t)s0 * LC;
        #pragma unroll
        for (int j = 0; j < NCH; ++j) {
            int c = lane + j * 32;
            if (c < LC) {
                float4 a = __ldg(&h0[c]);
                if (SRCSCALE) {
                    acc[j].x += a.x * c0; acc[j].y += a.y * c0;
                    acc[j].z += a.z * c0; acc[j].w += a.w * c0;
                } else {
                    acc[j].x += a.x; acc[j].y += a.y;
                    acc[j].z += a.z; acc[j].w += a.w;
                }
            }
        }
    }
}

// Fused pull + matmul for layers 1 and 2. One warp per node; tile staged in
// padded smem (row stride FIN+4 floats -> conflict-free t-strided reads).
// yout[n,t,:] = act((inorm[n] * agg[n,t,:]) @ W + b) * (OSCALE ? onorm[n] : 1)
template<int FIN, int FOUT, bool SRCSCALE, bool RELU, bool OSCALE>
__global__ void k_pullmm(const float* __restrict__ hin, const float* __restrict__ W,
                         const float* __restrict__ b, float* __restrict__ yout) {
    constexpr int LC  = T_DIM * FIN / 4;   // float4 chunks per node tile
    constexpr int NCH = (LC + 31) / 32;
    constexpr int QF  = FIN / 4;           // float4s per row
    constexpr int RS4 = QF + 1;            // padded row stride (float4)
    constexpr int RSF = FIN + 4;           // padded row stride (floats)
    constexpr int OG  = FOUT / 4;
    __shared__ float xsh[8][T_DIM * RSF];

    int warp = threadIdx.x >> 5, lane = threadIdx.x & 31;
    int node = blockIdx.x * 8 + warp;      // 50000 = 6250*8 exact

    float4 acc[NCH];
    pull_node<LC, NCH, SRCSCALE>(hin, node, lane, acc);

    float inrm = __ldg(&g_inorm[node]);
    float4* xs4 = reinterpret_cast<float4*>(xsh[warp]);
    #pragma unroll
    for (int j = 0; j < NCH; ++j) {
        int c = lane + j * 32;
        if (c < LC) {
            int t = c / QF, fq = c % QF;
            float4 v = acc[j];
            v.x *= inrm; v.y *= inrm; v.z *= inrm; v.w *= inrm;
            xs4[t * RS4 + fq] = v;
        }
    }
    __syncwarp();

    const float4* W4 = reinterpret_cast<const float4*>(W);
    for (int p = lane; p < T_DIM * OG; p += 32) {
        int t = p / OG, og = p % OG;
        float4 o = reinterpret_cast<const float4*>(b)[og];
        const float* xr = &xsh[warp][t * RSF];
        #pragma unroll 8
        for (int i = 0; i < FIN; ++i) {
            float xv = xr[i];
            float4 w = __ldg(&W4[i * OG + og]);
            o.x = fmaf(xv, w.x, o.x);
            o.y = fmaf(xv, w.y, o.y);
            o.z = fmaf(xv, w.z, o.z);
            o.w = fmaf(xv, w.w, o.w);
        }
        if (RELU) {
            o.x = fmaxf(o.x, 0.0f); o.y = fmaxf(o.y, 0.0f);
            o.z = fmaxf(o.z, 0.0f); o.w = fmaxf(o.w, 0.0f);
        }
        if (OSCALE) {
            float on = __ldg(&g_onorm[node]);
            o.x *= on; o.y *= on; o.z *= on; o.w *= on;
        }
        reinterpret_cast<float4*>(yout + (size_t)node * (T_DIM * FOUT) + t * FOUT)[og] = o;
    }
}

// Fused layer 3: pull + matmul (64->64, no act, no oscale) + conv1d(k=3,pad=1).
// All warp-local. xsh reused as the conv output staging buffer (sized 576).
__global__ void k_pullmm3_conv(const float* __restrict__ hin, const float* __restrict__ W,
                               const float* __restrict__ b, const float* __restrict__ bc,
                               float* __restrict__ out) {
    constexpr int FIN = 64, LC = 128, NCH = 4, QF = 16, RS4 = 17, RSF = 68;
    __shared__ float xsh[8][576];            // [t][f] padded (544 used) / then [o][t] pad-9
    __shared__ float ysh[8][T_DIM * RSF];    // matmul output, padded rows

    int warp = threadIdx.x >> 5, lane = threadIdx.x & 31;
    int node = blockIdx.x * 8 + warp;

    float4 acc[NCH];
    pull_node<LC, NCH, false>(hin, node, lane, acc);

    float inrm = __ldg(&g_inorm[node]);
    float4* xs4 = reinterpret_cast<float4*>(xsh[warp]);
    #pragma unroll
    for (int j = 0; j < NCH; ++j) {
        int c = lane + j * 32;
        int t = c / QF, fq = c % QF;
        float4 v = acc[j];
        v.x *= inrm; v.y *= inrm; v.z *= inrm; v.w *= inrm;
        xs4[t * RS4 + fq] = v;
    }
    __syncwarp();

    // matmul 64 -> 64 into ysh
    const float4* W4 = reinterpret_cast<const float4*>(W);
    float4* ys4 = reinterpret_cast<float4*>(ysh[warp]);
    #pragma unroll
    for (int p = lane; p < T_DIM * 16; p += 32) {
        int t = p / 16, og = p % 16;
        float4 o = reinterpret_cast<const float4*>(b)[og];
        const float* xr = &xsh[warp][t * RSF];
        #pragma unroll 8
        for (int i = 0; i < FIN; ++i) {
            float xv = xr[i];
            float4 w = __ldg(&W4[i * 16 + og]);
            o.x = fmaf(xv, w.x, o.x);
            o.y = fmaf(xv, w.y, o.y);
            o.z = fmaf(xv, w.z, o.z);
            o.w = fmaf(xv, w.w, o.w);
        }
        ys4[t * RS4 + og] = o;
    }
    __syncwarp();   // xsh fully consumed; ysh complete

    // conv over t (k=3, pad=1); osh = xsh reused, layout [o][t] stride 9
    float* osh = xsh[warp];
    const float4* Wt4 = reinterpret_cast<const float4*>(g_WcT);
    #pragma unroll
    for (int p = lane; p < T_DIM * 16; p += 32) {
        int t = p / 16, og = p % 16;
        float4 o = reinterpret_cast<const float4*>(bc)[og];
        #pragma unroll
        for (int k = 0; k < 3; ++k) {
            int tr = t + k - 1;
            if (tr < 0 || tr >= T_DIM) continue;
            const float* xr = &ysh[warp][tr * RSF];
            #pragma unroll 8
            for (int i = 0; i < 64; ++i) {
                float xv = xr[i];
                float4 w = __ldg(&Wt4[(k * 64 + i) * 16 + og]);
                o.x = fmaf(xv, w.x, o.x);
                o.y = fmaf(xv, w.y, o.y);
                o.z = fmaf(xv, w.z, o.z);
                o.w = fmaf(xv, w.w, o.w);
            }
        }
        int o0 = og * 4;
        osh[(o0 + 0) * 9 + t] = o.x;
        osh[(o0 + 1) * 9 + t] = o.y;
        osh[(o0 + 2) * 9 + t] = o.z;
        osh[(o0 + 3) * 9 + t] = o.w;
    }
    __syncwarp();

    float* ob = out + (size_t)node * 512;
    #pragma unroll
    for (int k = 0; k < 16; ++k) {
        int j = lane + k * 32;
        ob[j] = osh[(j >> 3) * 9 + (j & 7)];
    }
}

// ---------------------------------------------------------------------------
extern "C" void kernel_launch(void* const* d_in, const int* in_sizes, int n_in,
                              void* d_out, int out_size) {
    const float* tf  = (const float*)d_in[0];
    const int*   src = (const int*)  d_in[1];
    const int*   dst = (const int*)  d_in[2];
    const float* W1  = (const float*)d_in[3];
    const float* b1  = (const float*)d_in[4];
    const float* W2  = (const float*)d_in[5];
    const float* b2  = (const float*)d_in[6];
    const float* W3  = (const float*)d_in[7];
    const float* b3  = (const float*)d_in[8];
    const float* Wc  = (const float*)d_in[9];
    const float* bc  = (const float*)d_in[10];
    float* out = (float*)d_out;

    float *bufA, *bufB;
    cudaGetSymbolAddress((void**)&bufA, g_bufA);
    cudaGetSymbolAddress((void**)&bufB, g_bufB);

    const int TB = 256;

    // CSR build + prologue
    k_prep <<<cdiv(N_NODES * 256, TB), TB>>>(tf);
    k_deg  <<<cdiv(N_EDGES, TB), TB>>>(src, dst);
    k_scan1<<<SCAN_NB, 1024>>>();
    k_scan2<<<1, 32>>>();
    k_scan3<<<cdiv(N_NODES + 3 * 64 * 64, TB), TB>>>(Wc);
    k_fill <<<cdiv(N_EDGES, TB), TB>>>(src, dst);

    // ---- layer 1: pull + (32 -> 40) relu, onorm pre-applied for layer 2 ----
    k_pullmm<32, 40, true, true, true><<<N_NODES / 8, TB>>>(bufA, W1, b1, bufB);

    // ---- layer 2: pull + (40 -> 64) relu, onorm pre-applied for layer 3 ----
    k_pullmm<40, 64, false, true, true><<<N_NODES / 8, TB>>>(bufB, W2, b2, bufA);

    // ---- layer 3: pull + (64 -> 64) + conv1d fused -> out [N, 64, 8] ----
    k_pullmm3_conv<<<N_NODES / 8, TB>>>(bufA, W3, b3, bc, out);
}